// round 8
// baseline (speedup 1.0000x reference)
#include <cuda_runtime.h>
#include <cuda_fp16.h>
#include <cstdint>

// ---------------- problem constants ----------------
#define BATCH   512
#define CH      1024
#define FSQ     196
#define NWAY    64
#define NPIX    (BATCH * FSQ)      // 100352
#define MTILE   256
#define NCTA    (NPIX / MTILE)     // 392 exact
#define THREADS 256

// smem: A = 8 warps x 2 bufs x 2048 B = 32KB ; B = 2 x 16KB = 32KB
#define A_TOTAL     32768
#define B_TILE_B    16384
#define SMEM_BYTES  (A_TOTAL + 2 * B_TILE_B)   // 65536 -> 2 CTAs/SM

// ---------------- device scratch ----------------
__device__ __align__(16) uint32_t g_pbp[32768];  // [kt][ks][nt][lane]{b0,b1} fp16x2
__device__ float  g_pn[NWAY];
__device__ double g_acc;

// ---------------- helpers ----------------
__device__ __forceinline__ void cpa16(uint32_t dst, const void* src) {
    asm volatile("cp.async.cg.shared.global [%0], [%1], 16;" :: "r"(dst), "l"(src));
}
#define CPA_COMMIT() asm volatile("cp.async.commit_group;" ::: "memory")

__device__ __forceinline__ uint32_t pack_f16x2(float lo, float hi) {
    uint32_t r;
    asm("cvt.rn.f16x2.f32 %0, %1, %2;" : "=r"(r) : "f"(hi), "f"(lo));
    return r;
}
__device__ __forceinline__ void mma16816(float* d, const uint32_t* a,
                                         uint32_t b0, uint32_t b1) {
    asm volatile(
        "mma.sync.aligned.m16n8k16.row.col.f32.f16.f16.f32 "
        "{%0,%1,%2,%3}, {%4,%5,%6,%7}, {%8,%9}, {%0,%1,%2,%3};"
        : "+f"(d[0]), "+f"(d[1]), "+f"(d[2]), "+f"(d[3])
        : "r"(a[0]), "r"(a[1]), "r"(a[2]), "r"(a[3]), "r"(b0), "r"(b1));
}
__device__ __forceinline__ float lds32(uint32_t a) {
    float v;
    asm("ld.shared.f32 %0, [%1];" : "=f"(v) : "r"(a));
    return v;
}

// ---------------- prep: pack protos (fp16) into fragment order -------------
__global__ void dfmn_prep_kernel(const float* __restrict__ protos,
                                 const int*   __restrict__ indices) {
    const int n  = blockIdx.x;           // episode class 0..63
    const int kp = threadIdx.x;          // k-pair 0..511
    const int src = indices[n];
    const int k  = 2 * kp;

    float v0 = protos[(size_t)src * CH + k];
    float v1 = protos[(size_t)src * CH + k + 1];

    uint32_t h = pack_f16x2(v0, v1);

    const int kt = k >> 7, ks = (k >> 4) & 7, kk = k & 15;
    const int breg = kk >> 3, i = (kk >> 1) & 3;
    const int g = n & 7, nt = n >> 3;
    const int lane = g * 4 + i;
    const int base = (((kt * 8 + ks) * 8 + nt) * 256) / 4 + lane * 2;
    g_pbp[base + breg] = h;

    float ss = v0 * v0 + v1 * v1;
    #pragma unroll
    for (int o = 16; o > 0; o >>= 1)
        ss += __shfl_down_sync(0xffffffffu, ss, o);
    __shared__ float ws[16];
    if ((kp & 31) == 0) ws[kp >> 5] = ss;
    __syncthreads();
    if (kp == 0) {
        float s = 0.f;
        #pragma unroll
        for (int w = 0; w < 16; w++) s += ws[w];
        g_pn[n] = s;
        if (n == 0) g_acc = 0.0;
    }
}

// ---------------- main kernel ----------------
__global__ __launch_bounds__(THREADS, 2)
void dfmn_main_kernel(const float* __restrict__ q,
                      const int*   __restrict__ labels) {
    extern __shared__ __align__(16) char smraw[];
    const uint32_t smb   = (uint32_t)__cvta_generic_to_shared(smraw);
    const uint32_t Bbase = smb + A_TOTAL;
    __shared__ float s_pn[NWAY];
    __shared__ float s_ws[8];

    const int tid  = threadIdx.x;
    const int w    = tid >> 5;
    const int lane = tid & 31;
    const int g    = lane >> 2;
    const int i    = lane & 3;

    if (tid < NWAY) s_pn[tid] = g_pn[tid];

    const int warpPix = blockIdx.x * MTILE + w * 32;

    // ---- A cp.async setup: 4 chunks per lane (k0, k0+4, k0+8, k0+12) ----
    const int k0 = lane >> 3;            // 0..3
    const int cc = lane & 7;             // 0..7
    const int p0c  = warpPix + cc * 4;
    const int imgA = p0c / FSQ;
    const int iiA  = p0c - imgA * FSQ;
    const char* a_src0 = (const char*)(q + ((size_t)imgA * CH + k0) * FSQ + iiA);
    uint32_t a_dst[4];
    #pragma unroll
    for (int j = 0; j < 4; j++) {
        int k = k0 + 4 * j;
        a_dst[j] = (uint32_t)(k * 128 + ((cc * 16) ^ (((((unsigned)k) >> 1) & 3u) << 5)));
    }
    const uint32_t awbase = smb + w * 4096;   // 2 bufs x 2048 per warp

    auto issueA = [&](int s) {
        uint32_t dstb = awbase + (s & 1) * 2048;
        const char* srcs = a_src0 + (size_t)s * (16 * FSQ * 4);
        #pragma unroll
        for (int j = 0; j < 4; j++)
            cpa16(dstb + a_dst[j], srcs + (size_t)(4 * j) * (FSQ * 4));
    };
    auto issueB = [&](int kt) {
        const char* src = (const char*)g_pbp + (size_t)kt * B_TILE_B + tid * 16;
        uint32_t dst = Bbase + (kt & 1) * B_TILE_B + tid * 16;
        #pragma unroll
        for (int j = 0; j < 4; j++)
            cpa16(dst + j * 4096, src + j * 4096);
    };

    // ---- accumulators: 2 m16 tiles x 8 n-tiles x 4 regs ----
    float acc[2][8][4];
    #pragma unroll
    for (int t = 0; t < 2; t++)
        #pragma unroll
        for (int nt = 0; nt < 8; nt++)
            #pragma unroll
            for (int r = 0; r < 4; r++) acc[t][nt][r] = 0.f;

    // prologue: G0{A0,B0}, G1{A1,B1}
    issueA(0); issueB(0); CPA_COMMIT();
    issueA(1); issueB(1); CPA_COMMIT();

    const uint32_t arow = awbase + (uint32_t)(i * 256);
    uint32_t aoff[4];
    #pragma unroll
    for (int r = 0; r < 4; r++) aoff[r] = (uint32_t)(g * 4 + 32 * (r ^ i));

    for (int s = 0; s < 64; s++) {
        asm volatile("cp.async.wait_group 1;" ::: "memory");
        if ((s & 7) == 0) __syncthreads(); else __syncwarp();

        // ---- A fragments (single-pass fp16) ----
        const uint32_t ab = arow + (uint32_t)((s & 1) * 2048);
        uint32_t ah[2][4];
        #pragma unroll
        for (int r = 0; r < 4; r++) {
            float f0 = lds32(ab + aoff[r]);              // k=2i
            float f1 = lds32(ab + aoff[r] + 128);        // k=2i+1
            float f2 = lds32(ab + aoff[r] + 1024);       // k=2i+8
            float f3 = lds32(ab + aoff[r] + 1152);       // k=2i+9
            const int t = r >> 1, rr = r & 1;
            ah[t][rr]     = pack_f16x2(f0, f1);
            ah[t][rr + 2] = pack_f16x2(f2, f3);
        }

        // issue next tiles AFTER this warp's LDS reads (WAR gap >= L2 latency)
        const int m = s + 2;
        if (m < 64) {
            issueA(m);
            if ((m & 7) == 0) issueB(m >> 3);
        }
        CPA_COMMIT();

        // ---- B + MMAs: single qh . ph pass ----
        const uint32_t bb = Bbase + (uint32_t)(((s >> 3) & 1) * B_TILE_B
                                    + (s & 7) * 2048 + lane * 8);
        #pragma unroll
        for (int nt = 0; nt < 8; nt++) {
            uint32_t bh0, bh1;
            asm("ld.shared.v2.u32 {%0,%1}, [%2];"
                : "=r"(bh0), "=r"(bh1) : "r"(bb + nt * 256));
            mma16816(acc[0][nt], ah[0], bh0, bh1);
            mma16816(acc[1][nt], ah[1], bh0, bh1);
        }
    }

    // ---------------- fused log-softmax epilogue (4 pixels/thread) --------
    float loss = 0.f;
    #pragma unroll
    for (int r = 0; r < 4; r++) {
        const int P  = warpPix + g + 8 * r;
        const int bI = P / FSQ;
        const int Lv = labels[bI];
        const int t = r >> 1, pr = r & 1;

        float sv[16];
        float mx = -1e30f;
        #pragma unroll
        for (int nt = 0; nt < 8; nt++) {
            float v0 = 2.f * acc[t][nt][2 * pr]     - s_pn[nt * 8 + 2 * i];
            float v1 = 2.f * acc[t][nt][2 * pr + 1] - s_pn[nt * 8 + 2 * i + 1];
            sv[2 * nt] = v0; sv[2 * nt + 1] = v1;
            mx = fmaxf(mx, fmaxf(v0, v1));
        }
        mx = fmaxf(mx, __shfl_xor_sync(0xffffffffu, mx, 1));
        mx = fmaxf(mx, __shfl_xor_sync(0xffffffffu, mx, 2));
        float e = 0.f, sl = 0.f;
        #pragma unroll
        for (int nt = 0; nt < 8; nt++) {
            e += __expf(sv[2 * nt] - mx) + __expf(sv[2 * nt + 1] - mx);
            const int c0 = nt * 8 + 2 * i;
            if (c0 == Lv)     sl = sv[2 * nt];
            if (c0 + 1 == Lv) sl = sv[2 * nt + 1];
        }
        e  += __shfl_xor_sync(0xffffffffu, e, 1);
        e  += __shfl_xor_sync(0xffffffffu, e, 2);
        sl += __shfl_xor_sync(0xffffffffu, sl, 1);
        sl += __shfl_xor_sync(0xffffffffu, sl, 2);
        if (i == 0) loss += mx + __logf(e) - sl;
    }

    #pragma unroll
    for (int o = 16; o > 0; o >>= 1)
        loss += __shfl_down_sync(0xffffffffu, loss, o);
    if (lane == 0) s_ws[w] = loss;
    __syncthreads();
    if (tid == 0) {
        float s = 0.f;
        #pragma unroll
        for (int ww = 0; ww < 8; ww++) s += s_ws[ww];
        atomicAdd(&g_acc, (double)s);
    }
}

// ---------------- finalize ----------------
__global__ void dfmn_finalize_kernel(float* out) {
    out[0] = (float)(g_acc * (1.0 / (double)NPIX));
}

// ---------------- launch ----------------
extern "C" void kernel_launch(void* const* d_in, const int* in_sizes, int n_in,
                              void* d_out, int out_size) {
    const float* query   = (const float*)d_in[0];   // [512,1024,14,14] f32
    const int*   labels  = (const int*)  d_in[1];   // [512] i32
    const float* protos  = (const float*)d_in[2];   // [100,1024] f32
    const int*   indices = (const int*)  d_in[3];   // [64] i32
    float* out = (float*)d_out;

    cudaFuncSetAttribute(dfmn_main_kernel,
                         cudaFuncAttributeMaxDynamicSharedMemorySize,
                         SMEM_BYTES);

    dfmn_prep_kernel<<<NWAY, 512>>>(protos, indices);
    dfmn_main_kernel<<<NCTA, THREADS, SMEM_BYTES>>>(query, labels);
    dfmn_finalize_kernel<<<1, 1>>>(out);
}

// round 9
// speedup vs baseline: 1.2084x; 1.2084x over previous
#include <cuda_runtime.h>
#include <cuda_fp16.h>
#include <cstdint>

// ---------------- problem constants ----------------
#define BATCH   512
#define CH      1024
#define FSQ     196
#define NWAY    64
#define NPIX    (BATCH * FSQ)      // 100352
#define MTILE   256
#define NCTA    (NPIX / MTILE)     // 392 exact
#define THREADS 256

// smem: A = 8 warps x 4 bufs x 2048 B = 64KB ; B = 2 x 16KB = 32KB
// total 96KB -> 2 CTAs/SM (192KB <= 228KB)
#define A_TOTAL     65536
#define B_TILE_B    16384
#define SMEM_BYTES  (A_TOTAL + 2 * B_TILE_B)   // 98304

// ---------------- device scratch ----------------
__device__ __align__(16) uint32_t g_pbp[32768];  // [kt][ks][nt][lane]{b0,b1} fp16x2
__device__ float  g_pn[NWAY];
__device__ double g_acc;

// ---------------- helpers ----------------
__device__ __forceinline__ void cpa16(uint32_t dst, const void* src) {
    asm volatile("cp.async.cg.shared.global [%0], [%1], 16;" :: "r"(dst), "l"(src));
}
#define CPA_COMMIT() asm volatile("cp.async.commit_group;" ::: "memory")

__device__ __forceinline__ uint32_t pack_f16x2(float lo, float hi) {
    uint32_t r;
    asm("cvt.rn.f16x2.f32 %0, %1, %2;" : "=r"(r) : "f"(hi), "f"(lo));
    return r;
}
__device__ __forceinline__ void mma16816(float* d, const uint32_t* a,
                                         uint32_t b0, uint32_t b1) {
    asm volatile(
        "mma.sync.aligned.m16n8k16.row.col.f32.f16.f16.f32 "
        "{%0,%1,%2,%3}, {%4,%5,%6,%7}, {%8,%9}, {%0,%1,%2,%3};"
        : "+f"(d[0]), "+f"(d[1]), "+f"(d[2]), "+f"(d[3])
        : "r"(a[0]), "r"(a[1]), "r"(a[2]), "r"(a[3]), "r"(b0), "r"(b1));
}
__device__ __forceinline__ float lds32(uint32_t a) {
    float v;
    asm("ld.shared.f32 %0, [%1];" : "=f"(v) : "r"(a));
    return v;
}

// ---------------- prep: pack protos (fp16) into fragment order -------------
__global__ void dfmn_prep_kernel(const float* __restrict__ protos,
                                 const int*   __restrict__ indices) {
    const int n  = blockIdx.x;           // episode class 0..63
    const int kp = threadIdx.x;          // k-pair 0..511
    const int src = indices[n];
    const int k  = 2 * kp;

    float v0 = protos[(size_t)src * CH + k];
    float v1 = protos[(size_t)src * CH + k + 1];

    uint32_t h = pack_f16x2(v0, v1);

    const int kt = k >> 7, ks = (k >> 4) & 7, kk = k & 15;
    const int breg = kk >> 3, i = (kk >> 1) & 3;
    const int g = n & 7, nt = n >> 3;
    const int lane = g * 4 + i;
    const int base = (((kt * 8 + ks) * 8 + nt) * 256) / 4 + lane * 2;
    g_pbp[base + breg] = h;

    float ss = v0 * v0 + v1 * v1;
    #pragma unroll
    for (int o = 16; o > 0; o >>= 1)
        ss += __shfl_down_sync(0xffffffffu, ss, o);
    __shared__ float ws[16];
    if ((kp & 31) == 0) ws[kp >> 5] = ss;
    __syncthreads();
    if (kp == 0) {
        float s = 0.f;
        #pragma unroll
        for (int w = 0; w < 16; w++) s += ws[w];
        g_pn[n] = s;
        if (n == 0) g_acc = 0.0;
    }
}

// ---------------- main kernel ----------------
__global__ __launch_bounds__(THREADS, 2)
void dfmn_main_kernel(const float* __restrict__ q,
                      const int*   __restrict__ labels) {
    extern __shared__ __align__(16) char smraw[];
    const uint32_t smb   = (uint32_t)__cvta_generic_to_shared(smraw);
    const uint32_t Bbase = smb + A_TOTAL;
    __shared__ float s_pn[NWAY];
    __shared__ float s_ws[8];

    const int tid  = threadIdx.x;
    const int w    = tid >> 5;
    const int lane = tid & 31;
    const int g    = lane >> 2;
    const int i    = lane & 3;

    if (tid < NWAY) s_pn[tid] = g_pn[tid];

    const int warpPix = blockIdx.x * MTILE + w * 32;

    // ---- A cp.async setup: 4 chunks per lane (k0, k0+4, k0+8, k0+12) ----
    const int k0 = lane >> 3;            // 0..3
    const int cc = lane & 7;             // 0..7
    const int p0c  = warpPix + cc * 4;
    const int imgA = p0c / FSQ;
    const int iiA  = p0c - imgA * FSQ;
    const char* a_src0 = (const char*)(q + ((size_t)imgA * CH + k0) * FSQ + iiA);
    uint32_t a_dst[4];
    #pragma unroll
    for (int j = 0; j < 4; j++) {
        int k = k0 + 4 * j;
        a_dst[j] = (uint32_t)(k * 128 + ((cc * 16) ^ (((((unsigned)k) >> 1) & 3u) << 5)));
    }
    const uint32_t awbase = smb + w * 8192;   // 4 bufs x 2048 per warp

    auto issueA = [&](int s) {
        uint32_t dstb = awbase + (s & 3) * 2048;
        const char* srcs = a_src0 + (size_t)s * (16 * FSQ * 4);
        #pragma unroll
        for (int j = 0; j < 4; j++)
            cpa16(dstb + a_dst[j], srcs + (size_t)(4 * j) * (FSQ * 4));
    };
    auto issueB = [&](int kt) {
        const char* src = (const char*)g_pbp + (size_t)kt * B_TILE_B + tid * 16;
        uint32_t dst = Bbase + (kt & 1) * B_TILE_B + tid * 16;
        #pragma unroll
        for (int j = 0; j < 4; j++)
            cpa16(dst + j * 4096, src + j * 4096);
    };

    // ---- accumulators: 2 m16 tiles x 8 n-tiles x 4 regs ----
    float acc[2][8][4];
    #pragma unroll
    for (int t = 0; t < 2; t++)
        #pragma unroll
        for (int nt = 0; nt < 8; nt++)
            #pragma unroll
            for (int r = 0; r < 4; r++) acc[t][nt][r] = 0.f;

    issueA(0); issueB(0); CPA_COMMIT();
    issueA(1); CPA_COMMIT();
    issueA(2); CPA_COMMIT();

    const uint32_t arow = awbase + (uint32_t)(i * 256);
    uint32_t aoff[4];
    #pragma unroll
    for (int r = 0; r < 4; r++) aoff[r] = (uint32_t)(g * 4 + 32 * (r ^ i));

    for (int s = 0; s < 64; s++) {
        asm volatile("cp.async.wait_group 2;" ::: "memory");
        if ((s & 7) == 0) __syncthreads(); else __syncwarp();

        const int m = s + 3;
        if (m < 64) {
            issueA(m);
            if ((m & 7) == 0) issueB(m >> 3);
        }
        CPA_COMMIT();

        // ---- A fragments (single-pass fp16) ----
        const uint32_t ab = arow + (uint32_t)((s & 3) * 2048);
        uint32_t ah[2][4];
        #pragma unroll
        for (int r = 0; r < 4; r++) {
            float f0 = lds32(ab + aoff[r]);              // k=2i
            float f1 = lds32(ab + aoff[r] + 128);        // k=2i+1
            float f2 = lds32(ab + aoff[r] + 1024);       // k=2i+8
            float f3 = lds32(ab + aoff[r] + 1152);       // k=2i+9
            const int t = r >> 1, rr = r & 1;
            ah[t][rr]     = pack_f16x2(f0, f1);
            ah[t][rr + 2] = pack_f16x2(f2, f3);
        }

        // ---- B + MMAs: single qh . ph pass ----
        const uint32_t bb = Bbase + (uint32_t)(((s >> 3) & 1) * B_TILE_B
                                    + (s & 7) * 2048 + lane * 8);
        #pragma unroll
        for (int nt = 0; nt < 8; nt++) {
            uint32_t bh0, bh1;
            asm("ld.shared.v2.u32 {%0,%1}, [%2];"
                : "=r"(bh0), "=r"(bh1) : "r"(bb + nt * 256));
            mma16816(acc[0][nt], ah[0], bh0, bh1);
            mma16816(acc[1][nt], ah[1], bh0, bh1);
        }
    }

    // ---------------- fused log-softmax epilogue (4 pixels/thread) --------
    float loss = 0.f;
    #pragma unroll
    for (int r = 0; r < 4; r++) {
        const int P  = warpPix + g + 8 * r;
        const int bI = P / FSQ;
        const int Lv = labels[bI];
        const int t = r >> 1, pr = r & 1;

        float sv[16];
        float mx = -1e30f;
        #pragma unroll
        for (int nt = 0; nt < 8; nt++) {
            float v0 = 2.f * acc[t][nt][2 * pr]     - s_pn[nt * 8 + 2 * i];
            float v1 = 2.f * acc[t][nt][2 * pr + 1] - s_pn[nt * 8 + 2 * i + 1];
            sv[2 * nt] = v0; sv[2 * nt + 1] = v1;
            mx = fmaxf(mx, fmaxf(v0, v1));
        }
        mx = fmaxf(mx, __shfl_xor_sync(0xffffffffu, mx, 1));
        mx = fmaxf(mx, __shfl_xor_sync(0xffffffffu, mx, 2));
        float e = 0.f, sl = 0.f;
        #pragma unroll
        for (int nt = 0; nt < 8; nt++) {
            e += __expf(sv[2 * nt] - mx) + __expf(sv[2 * nt + 1] - mx);
            const int c0 = nt * 8 + 2 * i;
            if (c0 == Lv)     sl = sv[2 * nt];
            if (c0 + 1 == Lv) sl = sv[2 * nt + 1];
        }
        e  += __shfl_xor_sync(0xffffffffu, e, 1);
        e  += __shfl_xor_sync(0xffffffffu, e, 2);
        sl += __shfl_xor_sync(0xffffffffu, sl, 1);
        sl += __shfl_xor_sync(0xffffffffu, sl, 2);
        if (i == 0) loss += mx + __logf(e) - sl;
    }

    #pragma unroll
    for (int o = 16; o > 0; o >>= 1)
        loss += __shfl_down_sync(0xffffffffu, loss, o);
    if (lane == 0) s_ws[w] = loss;
    __syncthreads();
    if (tid == 0) {
        float s = 0.f;
        #pragma unroll
        for (int ww = 0; ww < 8; ww++) s += s_ws[ww];
        atomicAdd(&g_acc, (double)s);
    }
}

// ---------------- finalize ----------------
__global__ void dfmn_finalize_kernel(float* out) {
    out[0] = (float)(g_acc * (1.0 / (double)NPIX));
}

// ---------------- launch ----------------
extern "C" void kernel_launch(void* const* d_in, const int* in_sizes, int n_in,
                              void* d_out, int out_size) {
    const float* query   = (const float*)d_in[0];   // [512,1024,14,14] f32
    const int*   labels  = (const int*)  d_in[1];   // [512] i32
    const float* protos  = (const float*)d_in[2];   // [100,1024] f32
    const int*   indices = (const int*)  d_in[3];   // [64] i32
    float* out = (float*)d_out;

    cudaFuncSetAttribute(dfmn_main_kernel,
                         cudaFuncAttributeMaxDynamicSharedMemorySize,
                         SMEM_BYTES);

    dfmn_prep_kernel<<<NWAY, 512>>>(protos, indices);
    dfmn_main_kernel<<<NCTA, THREADS, SMEM_BYTES>>>(query, labels);
    dfmn_finalize_kernel<<<1, 1>>>(out);
}